// round 15
// baseline (speedup 1.0000x reference)
#include <cuda_runtime.h>

#define TBLOCK  128
#define NWARP   4
#define NFILT   11
#define NCOLS   262144
#define NROWS   128
#define WT      256                 // outputs per warp-tile (8 per lane)
#define TPW     4                   // tiles per warp (pipelined chain)
#define CH      68                  // float4 chunks per SoA array (67 used + pad)
#define NF4ROW  (NCOLS / 2)

typedef unsigned long long u64;

__device__ __forceinline__ u64 pack2(float lo, float hi) {
    u64 r; asm("mov.b64 %0, {%1, %2};" : "=l"(r) : "f"(lo), "f"(hi)); return r;
}
__device__ __forceinline__ void unpack2(u64 v, float& lo, float& hi) {
    asm("mov.b64 {%0, %1}, %2;" : "=f"(lo), "=f"(hi) : "l"(v));
}
__device__ __forceinline__ u64 fma2(u64 a, u64 b, u64 c) {
    u64 d; asm("fma.rn.f32x2 %0, %1, %2, %3;" : "=l"(d) : "l"(a), "l"(b), "l"(c)); return d;
}
__device__ __forceinline__ float4 ldz(const float4* x4, int u) {
    if (u >= 0 && u < NF4ROW) return __ldg(x4 + u);
    return make_float4(0.f, 0.f, 0.f, 0.f);
}
// XOR swizzle on chunk index: stride-2 chunk reads (d = 2*lane + q) conflict-free.
__device__ __forceinline__ int swz(int d) { return d ^ ((d >> 3) & 1); }

__global__ void __launch_bounds__(TBLOCK, 6) fir_w8_kernel(
    const float2* __restrict__ X, const float* __restrict__ phi,
    float2* __restrict__ Y)
{
    // Per-warp private double-buffered SoA slices, chunk-swizzled.
    // Array holds one float per complex; chunk c = floats [4c, 4c+3].
    __shared__ __align__(16) float4 s_re[NWARP][2][CH];
    __shared__ __align__(16) float4 s_im[NWARP][2][CH];

    const int lane = threadIdx.x & 31;
    const int wid  = threadIdx.x >> 5;
    const int row  = blockIdx.y;
    const float4* x4 = (const float4*)(X + (size_t)row * NCOLS);
    float2* yrow     = Y + (size_t)row * NCOLS;

    // Coefficients A[k] = (wr_k, wi_k) — phi's native layout.
    u64 A[NFILT];
#pragma unroll
    for (int k = 0; k < NFILT; k++) {
        float2 w = __ldg(((const float2*)phi) + k);
        A[k] = pack2(w.x, w.y);
    }

    // Warp chain: tiles [wt0, wt0+TPW), tile t covers cols [(wt0+t)*256, +256).
    const int wt0 = (blockIdx.x * NWARP + wid) * TPW;

    // Register stage: one tile = 134 gmem float4 chunks spread over the warp.
    float4 r0, r1, r2, r3, r4;

    // Tile t: window complexes [T0-6, T0+262), T0 = (wt0+t)*256.
    // gmem float4 m (rel) covers window complexes {2m, 2m+1}; g0 = T0/2 - 3.
    #define LOAD_TILE(t) do {                                      \
        const int g0 = (wt0 + (t)) * 128 - 3;                      \
        r0 = ldz(x4, g0 + lane);                                   \
        r1 = ldz(x4, g0 + 32 + lane);                              \
        r2 = ldz(x4, g0 + 64 + lane);                              \
        r3 = ldz(x4, g0 + 96 + lane);                              \
        r4 = (lane < 6) ? ldz(x4, g0 + 128 + lane)                 \
                        : make_float4(0.f, 0.f, 0.f, 0.f);         \
    } while (0)

    // Chunk m -> re float2 at float offset swz(m>>1)*4 + (m&1)*2 (swizzled), im same.
    #define PUT(pre, pim, m, v) do {                                         \
        const int off = swz((m) >> 1) * 4 + ((m) & 1) * 2;                   \
        *(float2*)((float*)(pre) + off) = make_float2((v).x, (v).z);         \
        *(float2*)((float*)(pim) + off) = make_float2((v).y, (v).w);         \
    } while (0)

    #define STORE_TILE(pre, pim) do {                 \
        PUT(pre, pim, lane,       r0);                \
        PUT(pre, pim, lane + 32,  r1);                \
        PUT(pre, pim, lane + 64,  r2);                \
        PUT(pre, pim, lane + 96,  r3);                \
        if (lane < 6) PUT(pre, pim, lane + 128, r4);  \
    } while (0)

    // ---- Prologue: tile 0 staged, tile 1 in registers ----
    LOAD_TILE(0);
    STORE_TILE(&s_re[wid][0][0], &s_im[wid][0][0]);
    LOAD_TILE(1);
    __syncwarp();

#pragma unroll
    for (int it = 0; it < TPW; ++it) {
        const int b = it & 1;

        if (it + 1 < TPW) {
            STORE_TILE(&s_re[wid][b ^ 1][0], &s_im[wid][b ^ 1][0]);
            if (it + 2 < TPW) LOAD_TILE(it + 2);
        }

        // ---- Compute tile `it`: 8 outputs per lane ----
        // Lane reads chunks d = 2*lane + q, q = 0..4 -> window complexes
        // [8*lane, 8*lane+19]. Output i (col T0+8l+i), tap k -> local jj = i+k+1.
        const float4* bre = &s_re[wid][b][0];
        const float4* bim = &s_im[wid][b][0];

        u64 P[8], Q[8];
#pragma unroll
        for (int i = 0; i < 8; i++) { P[i] = 0ull; Q[i] = 0ull; }

#pragma unroll
        for (int q = 0; q < 5; q++) {
            const float4 vr = bre[swz(2 * lane + q)];
            const float4 vi = bim[swz(2 * lane + q)];
            const float* fr = (const float*)&vr;
            const float* fi = (const float*)&vi;
#pragma unroll
            for (int h = 0; h < 4; h++) {
                const int jj = 4 * q + h;           // local complex offset 0..19
                if (jj < 1 || jj > 18) continue;    // compile-time prune
                const u64 xrr = pack2(fr[h], fr[h]);
                const u64 xii = pack2(fi[h], fi[h]);
#pragma unroll
                for (int i = 0; i < 8; i++) {
                    const int k = jj - 1 - i;       // compile-time after unroll
                    if (k >= 0 && k < NFILT) {
                        P[i] = fma2(xrr, A[k], P[i]);
                        Q[i] = fma2(xii, A[k], Q[i]);
                    }
                }
            }
        }

        // out = (P.lo - Q.hi, P.hi + Q.lo)
        const int c0 = (wt0 + it) * WT + 8 * lane;
        float4* yo = (float4*)(yrow + c0);
#pragma unroll
        for (int p = 0; p < 4; p++) {
            float ar, ai, br, bi2, cr, ci, dr, di;
            unpack2(P[2*p],   ar, ai); unpack2(Q[2*p],   br, bi2);
            unpack2(P[2*p+1], cr, ci); unpack2(Q[2*p+1], dr, di);
            float4 o;
            o.x = ar - bi2; o.y = ai + br;
            o.z = cr - di;  o.w = ci + dr;
            yo[p] = o;
        }

        __syncwarp();
    }
    #undef LOAD_TILE
    #undef STORE_TILE
    #undef PUT
}

extern "C" void kernel_launch(void* const* d_in, const int* in_sizes, int n_in,
                              void* d_out, int out_size)
{
    const float2* X   = (const float2*)d_in[0];
    const float*  phi = (const float*)d_in[1];
    float2*       Y   = (float2*)d_out;

    dim3 grid(NCOLS / (WT * NWARP * TPW), NROWS);   // (64, 128)
    fir_w8_kernel<<<grid, TBLOCK>>>(X, phi, Y);
}

// round 16
// speedup vs baseline: 1.1692x; 1.1692x over previous
#include <cuda_runtime.h>

#define TBLOCK  128
#define NWARP   4
#define NFILT   11
#define NCOLS   262144
#define NROWS   128
#define WTILE   128                 // outputs per warp-tile
#define TPW     4                   // tiles per warp (pipelined chain)
#define SWF     144                 // floats per array per warp slice (need 140)
#define NF4ROW  (NCOLS / 2)

typedef unsigned long long u64;

__device__ __forceinline__ u64 pack2(float lo, float hi) {
    u64 r; asm("mov.b64 %0, {%1, %2};" : "=l"(r) : "f"(lo), "f"(hi)); return r;
}
__device__ __forceinline__ void unpack2(u64 v, float& lo, float& hi) {
    asm("mov.b64 {%0, %1}, %2;" : "=f"(lo), "=f"(hi) : "l"(v));
}
__device__ __forceinline__ u64 fma2(u64 a, u64 b, u64 c) {
    u64 d; asm("fma.rn.f32x2 %0, %1, %2, %3;" : "=l"(d) : "l"(a), "l"(b), "l"(c)); return d;
}
// Non-coherent load with 256B L2 promotion: denser DRAM bursts for the read stream.
__device__ __forceinline__ float4 ldg256(const float4* p) {
    float4 v;
    asm volatile("ld.global.nc.L2::256B.v4.f32 {%0, %1, %2, %3}, [%4];"
                 : "=f"(v.x), "=f"(v.y), "=f"(v.z), "=f"(v.w) : "l"(p));
    return v;
}
__device__ __forceinline__ float4 ldz(const float4* x4, int u) {
    if (u >= 0 && u < NF4ROW) return ldg256(x4 + u);
    return make_float4(0.f, 0.f, 0.f, 0.f);
}
// Streaming (evict-first) 16B store: write-once output, keep it out of L2's way.
__device__ __forceinline__ void stg_cs(float2* p, float4 v) {
    asm volatile("st.global.cs.v4.f32 [%0], {%1, %2, %3, %4};"
                 :: "l"(p), "f"(v.x), "f"(v.y), "f"(v.z), "f"(v.w) : "memory");
}

__global__ void __launch_bounds__(TBLOCK, 10) fir_warp_final_kernel(
    const float2* __restrict__ X, const float* __restrict__ phi,
    float2* __restrict__ Y)
{
    // Per-warp private double-buffered SoA slices.
    __shared__ float s_re[NWARP][2][SWF];
    __shared__ float s_im[NWARP][2][SWF];

    const int lane = threadIdx.x & 31;
    const int wid  = threadIdx.x >> 5;
    const int row  = blockIdx.y;
    const float4* x4 = (const float4*)(X + (size_t)row * NCOLS);
    float2* yrow     = Y + (size_t)row * NCOLS;

    // Coefficients A[k] = (wr_k, wi_k) — phi's native layout.
    u64 A[NFILT];
#pragma unroll
    for (int k = 0; k < NFILT; k++) {
        float2 w = __ldg(((const float2*)phi) + k);
        A[k] = pack2(w.x, w.y);
    }

    // Warp's chain: tiles [wt0, wt0+TPW), tile t covers cols [(wt0+t)*128, +128).
    const int wt0 = (blockIdx.x * NWARP + wid) * TPW;

    float* const re0 = &s_re[wid][0][0];
    float* const im0 = &s_im[wid][0][0];
    float* const re1 = &s_re[wid][1][0];
    float* const im1 = &s_im[wid][1][0];

    float4 r0, r1, r2;   // register stage: one tile (72 gmem float4 over the warp)

    // Tile t: window complexes [T0-6, T0+138), T0 = (wt0+t)*128.
    // gmem float4 start g0 = T0/2 - 3. Lane loads g0+l, g0+32+l, (l<8) g0+64+l.
    #define LOAD_TILE(t) do {                                    \
        const int g0 = (wt0 + (t)) * 64 - 3;                     \
        r0 = ldz(x4, g0 + lane);                                 \
        r1 = ldz(x4, g0 + 32 + lane);                            \
        r2 = (lane < 8) ? ldz(x4, g0 + 64 + lane)                \
                        : make_float4(0.f, 0.f, 0.f, 0.f);       \
    } while (0)

    #define STORE_TILE(pre, pim) do {                                     \
        *(float2*)((pre) + 2 * lane)          = make_float2(r0.x, r0.z);  \
        *(float2*)((pim) + 2 * lane)          = make_float2(r0.y, r0.w);  \
        *(float2*)((pre) + 64 + 2 * lane)     = make_float2(r1.x, r1.z);  \
        *(float2*)((pim) + 64 + 2 * lane)     = make_float2(r1.y, r1.w);  \
        if (lane < 8) {                                                   \
            *(float2*)((pre) + 128 + 2 * lane) = make_float2(r2.x, r2.z); \
            *(float2*)((pim) + 128 + 2 * lane) = make_float2(r2.y, r2.w); \
        }                                                                 \
    } while (0)

    // ---- Prologue: tile 0 staged, tile 1 in registers ----
    LOAD_TILE(0);
    STORE_TILE(re0, im0);
    LOAD_TILE(1);
    __syncwarp();

#pragma unroll
    for (int it = 0; it < TPW; ++it) {
        float* const bre = (it & 1) ? re1 : re0;
        float* const bim = (it & 1) ? im1 : im0;

        if (it + 1 < TPW) {
            float* const nre = (it & 1) ? re0 : re1;
            float* const nim = (it & 1) ? im0 : im1;
            STORE_TILE(nre, nim);
            if (it + 2 < TPW) LOAD_TILE(it + 2);
        }

        // ---- Compute tile `it`: window floats [4l, 4l+15] of this warp's slice.
        // Output i (col T0 + 4l + i), tap k -> j = 4l + i + k + 1.
        float re[16], im[16];
        {
            const float4* pr = (const float4*)(bre + 4 * lane);
            const float4* pi = (const float4*)(bim + 4 * lane);
#pragma unroll
            for (int q = 0; q < 4; q++) {
                float4 vr = pr[q], vi = pi[q];
                re[4*q] = vr.x; re[4*q+1] = vr.y; re[4*q+2] = vr.z; re[4*q+3] = vr.w;
                im[4*q] = vi.x; im[4*q+1] = vi.y; im[4*q+2] = vi.z; im[4*q+3] = vi.w;
            }
        }

        u64 P[4], Q[4];
#pragma unroll
        for (int i = 0; i < 4; i++) { P[i] = 0ull; Q[i] = 0ull; }

#pragma unroll
        for (int j = 1; j <= 14; j++) {
            u64 xrr = pack2(re[j], re[j]);
            u64 xii = pack2(im[j], im[j]);
#pragma unroll
            for (int i = 0; i < 4; i++) {
                const int k = j - 1 - i;            // compile-time after unroll
                if (k >= 0 && k < NFILT) {
                    P[i] = fma2(xrr, A[k], P[i]);
                    Q[i] = fma2(xii, A[k], Q[i]);
                }
            }
        }

        // out = (P.lo - Q.hi, P.hi + Q.lo)
        const int c0 = (wt0 + it) * WTILE + 4 * lane;
        float4 o0, o1;
        float prr, pri, qir, qii;
        unpack2(P[0], prr, pri); unpack2(Q[0], qir, qii); o0.x = prr - qii; o0.y = pri + qir;
        unpack2(P[1], prr, pri); unpack2(Q[1], qir, qii); o0.z = prr - qii; o0.w = pri + qir;
        unpack2(P[2], prr, pri); unpack2(Q[2], qir, qii); o1.x = prr - qii; o1.y = pri + qir;
        unpack2(P[3], prr, pri); unpack2(Q[3], qir, qii); o1.z = prr - qii; o1.w = pri + qir;

        stg_cs(yrow + c0, o0);
        stg_cs(yrow + c0 + 2, o1);

        __syncwarp();   // orders this iter's STS before next iter's LDS
    }
    #undef LOAD_TILE
    #undef STORE_TILE
}

extern "C" void kernel_launch(void* const* d_in, const int* in_sizes, int n_in,
                              void* d_out, int out_size)
{
    const float2* X   = (const float2*)d_in[0];
    const float*  phi = (const float*)d_in[1];
    float2*       Y   = (float2*)d_out;

    dim3 grid(NCOLS / (WTILE * NWARP * TPW), NROWS);   // (128, 128)
    fir_warp_final_kernel<<<grid, TBLOCK>>>(X, phi, Y);
}

// round 17
// speedup vs baseline: 1.1727x; 1.0030x over previous
#include <cuda_runtime.h>

#define TBLOCK  128
#define NWARP   4
#define NFILT   11
#define NCOLS   262144
#define NROWS   128
#define WTILE   128                 // outputs per warp-tile
#define TPW     4                   // tiles per warp (pipelined chain)
#define SWF     144                 // floats per array per warp slice (need 140)
#define NF4ROW  (NCOLS / 2)

typedef unsigned long long u64;

__device__ __forceinline__ u64 pack2(float lo, float hi) {
    u64 r; asm("mov.b64 %0, {%1, %2};" : "=l"(r) : "f"(lo), "f"(hi)); return r;
}
__device__ __forceinline__ void unpack2(u64 v, float& lo, float& hi) {
    asm("mov.b64 {%0, %1}, %2;" : "=f"(lo), "=f"(hi) : "l"(v));
}
__device__ __forceinline__ u64 fma2(u64 a, u64 b, u64 c) {
    u64 d; asm("fma.rn.f32x2 %0, %1, %2, %3;" : "=l"(d) : "l"(a), "l"(b), "l"(c)); return d;
}
// Non-coherent load with 256B L2 promotion: denser DRAM bursts for the read stream.
__device__ __forceinline__ float4 ldg256(const float4* p) {
    float4 v;
    asm volatile("ld.global.nc.L2::256B.v4.f32 {%0, %1, %2, %3}, [%4];"
                 : "=f"(v.x), "=f"(v.y), "=f"(v.z), "=f"(v.w) : "l"(p));
    return v;
}
__device__ __forceinline__ float4 ldz(const float4* x4, int u) {
    if (u >= 0 && u < NF4ROW) return ldg256(x4 + u);
    return make_float4(0.f, 0.f, 0.f, 0.f);
}
// Streaming (evict-first) 16B store: write-once output, keep it out of L2's way.
__device__ __forceinline__ void stg_cs(float2* p, float4 v) {
    asm volatile("st.global.cs.v4.f32 [%0], {%1, %2, %3, %4};"
                 :: "l"(p), "f"(v.x), "f"(v.y), "f"(v.z), "f"(v.w) : "memory");
}

__global__ void __launch_bounds__(TBLOCK, 10) fir_warp_final_kernel(
    const float2* __restrict__ X, const float* __restrict__ phi,
    float2* __restrict__ Y)
{
    // Per-warp private double-buffered SoA slices.
    __shared__ float s_re[NWARP][2][SWF];
    __shared__ float s_im[NWARP][2][SWF];

    const int lane = threadIdx.x & 31;
    const int wid  = threadIdx.x >> 5;
    const int row  = blockIdx.y;
    const float4* x4 = (const float4*)(X + (size_t)row * NCOLS);
    float2* yrow     = Y + (size_t)row * NCOLS;

    // Coefficients A[k] = (wr_k, wi_k) — phi's native layout.
    u64 A[NFILT];
#pragma unroll
    for (int k = 0; k < NFILT; k++) {
        float2 w = __ldg(((const float2*)phi) + k);
        A[k] = pack2(w.x, w.y);
    }

    // Warp's chain: tiles [wt0, wt0+TPW), tile t covers cols [(wt0+t)*128, +128).
    const int wt0 = (blockIdx.x * NWARP + wid) * TPW;

    float* const re0 = &s_re[wid][0][0];
    float* const im0 = &s_im[wid][0][0];
    float* const re1 = &s_re[wid][1][0];
    float* const im1 = &s_im[wid][1][0];

    float4 r0, r1, r2;   // register stage: one tile (72 gmem float4 over the warp)

    // Tile t: window complexes [T0-6, T0+138), T0 = (wt0+t)*128.
    // gmem float4 start g0 = T0/2 - 3. Lane loads g0+l, g0+32+l, (l<8) g0+64+l.
    #define LOAD_TILE(t) do {                                    \
        const int g0 = (wt0 + (t)) * 64 - 3;                     \
        r0 = ldz(x4, g0 + lane);                                 \
        r1 = ldz(x4, g0 + 32 + lane);                            \
        r2 = (lane < 8) ? ldz(x4, g0 + 64 + lane)                \
                        : make_float4(0.f, 0.f, 0.f, 0.f);       \
    } while (0)

    #define STORE_TILE(pre, pim) do {                                     \
        *(float2*)((pre) + 2 * lane)          = make_float2(r0.x, r0.z);  \
        *(float2*)((pim) + 2 * lane)          = make_float2(r0.y, r0.w);  \
        *(float2*)((pre) + 64 + 2 * lane)     = make_float2(r1.x, r1.z);  \
        *(float2*)((pim) + 64 + 2 * lane)     = make_float2(r1.y, r1.w);  \
        if (lane < 8) {                                                   \
            *(float2*)((pre) + 128 + 2 * lane) = make_float2(r2.x, r2.z); \
            *(float2*)((pim) + 128 + 2 * lane) = make_float2(r2.y, r2.w); \
        }                                                                 \
    } while (0)

    // ---- Prologue: tile 0 staged, tile 1 in registers ----
    LOAD_TILE(0);
    STORE_TILE(re0, im0);
    LOAD_TILE(1);
    __syncwarp();

#pragma unroll
    for (int it = 0; it < TPW; ++it) {
        float* const bre = (it & 1) ? re1 : re0;
        float* const bim = (it & 1) ? im1 : im0;

        if (it + 1 < TPW) {
            float* const nre = (it & 1) ? re0 : re1;
            float* const nim = (it & 1) ? im0 : im1;
            STORE_TILE(nre, nim);
            if (it + 2 < TPW) LOAD_TILE(it + 2);
        }

        // ---- Compute tile `it`: window floats [4l, 4l+15] of this warp's slice.
        // Output i (col T0 + 4l + i), tap k -> j = 4l + i + k + 1.
        float re[16], im[16];
        {
            const float4* pr = (const float4*)(bre + 4 * lane);
            const float4* pi = (const float4*)(bim + 4 * lane);
#pragma unroll
            for (int q = 0; q < 4; q++) {
                float4 vr = pr[q], vi = pi[q];
                re[4*q] = vr.x; re[4*q+1] = vr.y; re[4*q+2] = vr.z; re[4*q+3] = vr.w;
                im[4*q] = vi.x; im[4*q+1] = vi.y; im[4*q+2] = vi.z; im[4*q+3] = vi.w;
            }
        }

        u64 P[4], Q[4];
#pragma unroll
        for (int i = 0; i < 4; i++) { P[i] = 0ull; Q[i] = 0ull; }

#pragma unroll
        for (int j = 1; j <= 14; j++) {
            u64 xrr = pack2(re[j], re[j]);
            u64 xii = pack2(im[j], im[j]);
#pragma unroll
            for (int i = 0; i < 4; i++) {
                const int k = j - 1 - i;            // compile-time after unroll
                if (k >= 0 && k < NFILT) {
                    P[i] = fma2(xrr, A[k], P[i]);
                    Q[i] = fma2(xii, A[k], Q[i]);
                }
            }
        }

        // out = (P.lo - Q.hi, P.hi + Q.lo)
        const int c0 = (wt0 + it) * WTILE + 4 * lane;
        float4 o0, o1;
        float prr, pri, qir, qii;
        unpack2(P[0], prr, pri); unpack2(Q[0], qir, qii); o0.x = prr - qii; o0.y = pri + qir;
        unpack2(P[1], prr, pri); unpack2(Q[1], qir, qii); o0.z = prr - qii; o0.w = pri + qir;
        unpack2(P[2], prr, pri); unpack2(Q[2], qir, qii); o1.x = prr - qii; o1.y = pri + qir;
        unpack2(P[3], prr, pri); unpack2(Q[3], qir, qii); o1.z = prr - qii; o1.w = pri + qir;

        stg_cs(yrow + c0, o0);
        stg_cs(yrow + c0 + 2, o1);

        __syncwarp();   // orders this iter's STS before next iter's LDS
    }
    #undef LOAD_TILE
    #undef STORE_TILE
}

extern "C" void kernel_launch(void* const* d_in, const int* in_sizes, int n_in,
                              void* d_out, int out_size)
{
    const float2* X   = (const float2*)d_in[0];
    const float*  phi = (const float*)d_in[1];
    float2*       Y   = (float2*)d_out;

    dim3 grid(NCOLS / (WTILE * NWARP * TPW), NROWS);   // (128, 128)
    fir_warp_final_kernel<<<grid, TBLOCK>>>(X, phi, Y);
}